// round 17
// baseline (speedup 1.0000x reference)
#include <cuda_runtime.h>
#include <cstdint>

// Monolithic-staging variant of the R8/R15 clean-mix design.
// out[o*256+k][h][m] = sum_{i,j} w[i][k][j] * xp[m+j], xp = padded/rolled row.
// Grid 112 = (o:2, kq:4, h:14). Block 1024 = 16 i-groups x 64 k; thread = one k,
// 7 f32x2 accumulators (all 14 m), 16 i's. ALL weights (192KB) staged via
// cp.async in 2 halves split by il<8 / il>=8 -> mainloop is two straight-line
// 8-il runs, 2 barriers total. Deterministic smem reduction.

#define W_FLOATS (256 * 192)             // SR[i][192] : 192KB
#define SXE_OFF  W_FLOATS                // sxe: 256 x 16 floats (16KB)
#define SXO_OFF  (SXE_OFF + 4096)        // sxo: 16KB
#define SMEM_FLOATS (SXO_OFF + 4096)     // 57344 floats = 224KB
#define SMEM_BYTES  (SMEM_FLOATS * 4)

extern __shared__ float smem[];

__device__ __forceinline__ uint64_t pk2(float v) {
    uint64_t r;
    asm("mov.b64 %0, {%1, %1};" : "=l"(r) : "r"(__float_as_uint(v)));
    return r;
}
__device__ __forceinline__ uint64_t ffma2(uint64_t a, uint64_t b, uint64_t c) {
    uint64_t d;
    asm("fma.rn.f32x2 %0, %1, %2, %3;" : "=l"(d) : "l"(a), "l"(b), "l"(c));
    return d;
}
__device__ __forceinline__ void cp16(uint32_t s, const void* g) {
    asm volatile("cp.async.cg.shared.global [%0], [%1], 16;" :: "r"(s), "l"(g) : "memory");
}
__device__ __forceinline__ void cp_commit() {
    asm volatile("cp.async.commit_group;" ::: "memory");
}
template <int N> __device__ __forceinline__ void cp_wait() {
    asm volatile("cp.async.wait_group %0;" :: "n"(N) : "memory");
}

__global__ __launch_bounds__(1024, 1)
void fused_conv_kernel(const float* __restrict__ x,
                       const float* __restrict__ w,
                       float* __restrict__ out) {
    const int bx = blockIdx.x;          // 0..111
    const int o  = bx / 56;
    const int kq = (bx / 14) & 3;       // 64-k quarter
    const int h  = bx % 14;
    const int tid = threadIdx.x;
    const int g   = tid >> 6;           // i-group 0..15 (16 i each)
    const int tx  = tid & 63;           // k within quarter
    const int n   = (h + 13) % 14;      // undo roll along H

    const uint32_t s_u32 = (uint32_t)__cvta_generic_to_shared(smem);
    const float* wb = w + (size_t)kq * 192;   // w[i][kq*64 + 0..63][0..2]

    // ---- cp.async weight copy: 2 halves split by il parity ----
    // half c covers il = c*8 .. c*8+7 for every group: rows r 0..127,
    // i = (r>>3)*16 + c*8 + (r&7); 48 f4 per row; 6144 f4 per half.
#define ISSUE_HALF(cc)                                                        \
    {                                                                         \
        _Pragma("unroll")                                                     \
        for (int it = 0; it < 6; it++) {                                      \
            const int f4  = it * 1024 + tid;                                  \
            const int r   = f4 / 48;                                          \
            const int col = f4 % 48;                                          \
            const int i   = (r >> 3) * 16 + (cc) * 8 + (r & 7);               \
            cp16(s_u32 + (uint32_t)(i * 192 + col * 4) * 4,                   \
                 wb + (size_t)i * 768 + col * 4);                             \
        }                                                                     \
        cp_commit();                                                          \
    }
    ISSUE_HALF(0)
    ISSUE_HALF(1)

    // ---- stage x: sxe[i][mm] = xp[mm], sxo[i][mm] = xp[mm+1]
    // xp[a] = (a in [1,14]) ? x[(o*256+i)*196 + n*14 + (a+12)%14] : 0
    {
        const float* xbase = x + ((size_t)o * 256) * 196 + n * 14;
#pragma unroll
        for (int rep = 0; rep < 4; rep++) {
            const int idx = rep * 1024 + tid;      // 0..4095
            const int i = idx >> 4;
            const int mm = idx & 15;
            float ve = 0.f, vo = 0.f;
            if (mm >= 1 && mm <= 14) ve = xbase[(size_t)i * 196 + (mm + 12) % 14];
            if (mm + 1 <= 14)        vo = xbase[(size_t)i * 196 + (mm + 13) % 14];
            smem[SXE_OFF + idx] = ve;
            smem[SXO_OFF + idx] = vo;
        }
    }

    uint64_t A[7];
#pragma unroll
    for (int p = 0; p < 7; p++) A[p] = 0ull;

    // ---- mainloop: two straight-line 8-il runs, 2 barriers total ----
#pragma unroll
    for (int half = 0; half < 2; half++) {
        if (half == 0) cp_wait<1>(); else cp_wait<0>();
        __syncthreads();                 // half's weights (+x staging on half 0) visible

#pragma unroll 4
        for (int q = 0; q < 8; q++) {
            const int il = half * 8 + q;
            const int i  = g * 16 + il;
            const float* swp = smem + (size_t)i * 192 + tx * 3;
            const float* xe  = smem + SXE_OFF + (size_t)i * 16;
            const float* xo  = smem + SXO_OFF + (size_t)i * 16;

            const uint64_t W0 = pk2(swp[0]);
            const uint64_t W1 = pk2(swp[1]);
            const uint64_t W2 = pk2(swp[2]);

            const ulonglong2 e01 = *(const ulonglong2*)(xe);
            const ulonglong2 e23 = *(const ulonglong2*)(xe + 4);
            const ulonglong2 e45 = *(const ulonglong2*)(xe + 8);
            const ulonglong2 e67 = *(const ulonglong2*)(xe + 12);
            const ulonglong2 o01 = *(const ulonglong2*)(xo);
            const ulonglong2 o23 = *(const ulonglong2*)(xo + 4);
            const ulonglong2 o45 = *(const ulonglong2*)(xo + 8);
            const uint64_t   o6  = *(const uint64_t*)  (xo + 12);

            uint64_t E[8] = {e01.x, e01.y, e23.x, e23.y, e45.x, e45.y, e67.x, e67.y};
            uint64_t O[7] = {o01.x, o01.y, o23.x, o23.y, o45.x, o45.y, o6};

#pragma unroll
            for (int p = 0; p < 7; p++) {
                A[p] = ffma2(W0, E[p],     A[p]);
                A[p] = ffma2(W1, O[p],     A[p]);
                A[p] = ffma2(W2, E[p + 1], A[p]);
            }
        }
    }

    // ---- cross-group reduction in smem ----
    __syncthreads();                     // all warps done reading weights
    uint64_t* ps = (uint64_t*)smem;      // ps[g*448 + tx*7 + p], 56KB
#pragma unroll
    for (int p = 0; p < 7; p++)
        ps[(size_t)g * 448 + tx * 7 + p] = A[p];
    __syncthreads();

    if (tid < 448) {
        const int k = tid / 7;           // 0..63
        const int p = tid % 7;
        float vlo = 0.f, vhi = 0.f;
#pragma unroll
        for (int gg = 0; gg < 16; gg++) { // fixed order -> deterministic
            const float2 v = ((const float2*)ps)[gg * 448 + k * 7 + p];
            vlo += v.x;
            vhi += v.y;
        }
        const int cg = o * 256 + kq * 64 + k;
        float2 s; s.x = vlo; s.y = vhi;
        *(float2*)&out[(size_t)cg * 196 + h * 14 + 2 * p] = s;
    }
}

extern "C" void kernel_launch(void* const* d_in, const int* in_sizes, int n_in,
                              void* d_out, int out_size) {
    const float* x = (const float*)d_in[0];   // (1,512,14,14)
    const float* w = (const float*)d_in[1];   // (256,256,3)
    float* out = (float*)d_out;

    cudaFuncSetAttribute(fused_conv_kernel,
                         cudaFuncAttributeMaxDynamicSharedMemorySize, SMEM_BYTES);
    fused_conv_kernel<<<112, 1024, SMEM_BYTES>>>(x, w, out);
}